// round 13
// baseline (speedup 1.0000x reference)
#include <cuda_runtime.h>

#define BATCH 512
#define SEQ   1024
#define NTAGS 64

#define L2E 1.4426950408889634f
#define LN2 0.6931471805599453f

typedef unsigned long long ull;

__device__ float g_logz[BATCH];
__device__ float g_score[BATCH];

// ---------- packed f32x2 + MUFU helpers (sm_103a) ----------
__device__ __forceinline__ ull pack2(float a, float b) {
    ull r;
    unsigned ia = __float_as_uint(a), ib = __float_as_uint(b);
    asm("mov.b64 %0, {%1,%2};" : "=l"(r) : "r"(ia), "r"(ib));
    return r;
}
__device__ __forceinline__ void unpack2(ull v, float& a, float& b) {
    unsigned ia, ib;
    asm("mov.b64 {%0,%1}, %2;" : "=r"(ia), "=r"(ib) : "l"(v));
    a = __uint_as_float(ia);
    b = __uint_as_float(ib);
}
__device__ __forceinline__ ull fma2(ull a, ull b, ull c) {
    ull d;
    asm("fma.rn.f32x2 %0, %1, %2, %3;" : "=l"(d) : "l"(a), "l"(b), "l"(c));
    return d;
}
__device__ __forceinline__ ull add2(ull a, ull b) {
    ull d;
    asm("add.rn.f32x2 %0, %1, %2;" : "=l"(d) : "l"(a), "l"(b));
    return d;
}
__device__ __forceinline__ float ex2f(float x) {
    float r; asm("ex2.approx.f32 %0, %1;" : "=f"(r) : "f"(x)); return r;
}
__device__ __forceinline__ float lg2f(float x) {
    float r; asm("lg2.approx.f32 %0, %1;" : "=f"(r) : "f"(x)); return r;
}
__device__ __forceinline__ float rcpf(float x) {
    float r; asm("rcp.approx.f32 %0, %1;" : "=f"(r) : "f"(x)); return r;
}

// ---------- one step, TWO batches, pair-split dot (probability domain) ----
// 128 threads/block: thread = (tag j = tid>>1, half = tid&1).
// Half h sums i in [32h, 32h+32); shfl_xor(1) combines -> BOTH pair threads
// hold the full a_j, so stores are unconditional (per-half duplicate copies,
// one writer per address, no branches anywhere).
// Invariant: true_log2_alpha_j = lg2(a_j) + Bacc (per batch, Bacc uniform).
__device__ __forceinline__ void crf_step2(
    float eemX, float eemY, int mkX, int mkY, int par,
    float& aX, float& aY, float& BaccX, float& BaccY,
    const ull (&Epair)[16],
    float (&pbuf)[2][2][2][64],
    int j, int half)
{
    pbuf[par][0][half][j] = aX;    // duplicated per-half copies: no conflicts
    pbuf[par][1][half][j] = aY;
    __syncthreads();
    float a0X = pbuf[par][0][half][0];
    float a0Y = pbuf[par][1][half][0];
    const int ib = half << 5;
    const ulonglong2* pvX = reinterpret_cast<const ulonglong2*>(&pbuf[par][0][half][ib]);
    const ulonglong2* pvY = reinterpret_cast<const ulonglong2*>(&pbuf[par][1][half][ib]);
    ull sA = 0ull, sB = 0ull, sC = 0ull, sD = 0ull;   // X: 4 chains
    ull tA = 0ull, tB = 0ull, tC = 0ull, tD = 0ull;   // Y: 4 chains
#pragma unroll
    for (int k = 0; k < 8; k += 2) {
        ulonglong2 qa = pvX[k];
        ulonglong2 qb = pvX[k + 1];
        ulonglong2 ra = pvY[k];
        ulonglong2 rb = pvY[k + 1];
        sA = fma2(qa.x, Epair[2 * k],     sA);
        tA = fma2(ra.x, Epair[2 * k],     tA);
        sB = fma2(qa.y, Epair[2 * k + 1], sB);
        tB = fma2(ra.y, Epair[2 * k + 1], tB);
        sC = fma2(qb.x, Epair[2 * k + 2], sC);
        tC = fma2(rb.x, Epair[2 * k + 2], tC);
        sD = fma2(qb.y, Epair[2 * k + 3], sD);
        tD = fma2(rb.y, Epair[2 * k + 3], tD);
    }
    float raX = rcpf(a0X), laX = lg2f(a0X);   // off the dot critical path
    float raY = rcpf(a0Y), laY = lg2f(a0Y);
    ull sP = add2(add2(sA, sB), add2(sC, sD));
    ull tP = add2(add2(tA, tB), add2(tC, tD));
    float xlo, xhi, ylo, yhi;
    unpack2(sP, xlo, xhi);
    unpack2(tP, ylo, yhi);
    float sX = xlo + xhi;
    float sY = ylo + yhi;
    sX += __shfl_xor_sync(0xffffffffu, sX, 1);   // combine halves (back-to-back,
    sY += __shfl_xor_sync(0xffffffffu, sY, 1);   //  latencies overlap)
    float nX = sX * (eemX * raX);
    float nY = sY * (eemY * raY);
    bool uX = (mkX != 0), uY = (mkY != 0);
    aX    = uX ? nX : aX;                        // SELs only
    BaccX = uX ? (BaccX + laX) : BaccX;
    aY    = uY ? nY : aY;
    BaccY = uY ? (BaccY + laY) : BaccY;
}

// ---------- forward algorithm: 2 batches per 128-thread block ----------
__global__ void __launch_bounds__(128, 1)
forward_kernel(const float* __restrict__ em,
               const float* __restrict__ startt,
               const float* __restrict__ endt,
               const float* __restrict__ trans,
               const int* __restrict__ mask)
{
    __shared__ __align__(16) float pbuf[2][2][2][64];  // [par][batch][half][tag]
    __shared__ float vredX[NTAGS], vredY[NTAGS];

    const int bX = 2 * blockIdx.x;
    const int bY = bX + 1;
    const int tid = threadIdx.x;
    const int j = tid >> 1;
    const int half = tid & 1;
    const int ibase = half << 5;

    // E slice: exp(T[i][j]) for i in [ibase, ibase+32), packed f32x2 (32 regs).
    ull Epair[16];
#pragma unroll
    for (int k = 0; k < 16; ++k) {
        float ea = __expf(trans[(ibase + 2 * k)     * NTAGS + j]);
        float eb = __expf(trans[(ibase + 2 * k + 1) * NTAGS + j]);
        Epair[k] = pack2(ea, eb);
    }

    const float* emX = em + (size_t)bX * SEQ * NTAGS + j;
    const float* emY = em + (size_t)bY * SEQ * NTAGS + j;
    const int* mkX = mask + (size_t)bX * SEQ;
    const int* mkY = mask + (size_t)bY * SEQ;

    float st = startt[j] * L2E;
    float aX = ex2f(st + emX[0] * L2E);   // both pair threads identical
    float aY = ex2f(st + emY[0] * L2E);
    float BaccX = 0.0f, BaccY = 0.0f;

    // Prefetch rings, distance 4: exp(em) computed off the chain.
    float fX0 = ex2f(emX[(size_t)1 * NTAGS] * L2E);
    float fX1 = ex2f(emX[(size_t)2 * NTAGS] * L2E);
    float fX2 = ex2f(emX[(size_t)3 * NTAGS] * L2E);
    float fX3 = ex2f(emX[(size_t)4 * NTAGS] * L2E);
    float fY0 = ex2f(emY[(size_t)1 * NTAGS] * L2E);
    float fY1 = ex2f(emY[(size_t)2 * NTAGS] * L2E);
    float fY2 = ex2f(emY[(size_t)3 * NTAGS] * L2E);
    float fY3 = ex2f(emY[(size_t)4 * NTAGS] * L2E);
    int mX0 = mkX[1], mX1 = mkX[2], mX2 = mkX[3], mX3 = mkX[4];
    int mY0 = mkY[1], mY1 = mkY[2], mY2 = mkY[3], mY3 = mkY[4];

    for (int t0 = 1; t0 + 7 < SEQ; t0 += 4) {
        float eX0 = fX0, eX1 = fX1, eX2 = fX2, eX3 = fX3;
        float eY0 = fY0, eY1 = fY1, eY2 = fY2, eY3 = fY3;
        int qX0 = mX0, qX1 = mX1, qX2 = mX2, qX3 = mX3;
        int qY0 = mY0, qY1 = mY1, qY2 = mY2, qY3 = mY3;
        int tn = t0 + 4;
        fX0 = ex2f(emX[(size_t)(tn + 0) * NTAGS] * L2E); mX0 = mkX[tn + 0];
        fX1 = ex2f(emX[(size_t)(tn + 1) * NTAGS] * L2E); mX1 = mkX[tn + 1];
        fX2 = ex2f(emX[(size_t)(tn + 2) * NTAGS] * L2E); mX2 = mkX[tn + 2];
        fX3 = ex2f(emX[(size_t)(tn + 3) * NTAGS] * L2E); mX3 = mkX[tn + 3];
        fY0 = ex2f(emY[(size_t)(tn + 0) * NTAGS] * L2E); mY0 = mkY[tn + 0];
        fY1 = ex2f(emY[(size_t)(tn + 1) * NTAGS] * L2E); mY1 = mkY[tn + 1];
        fY2 = ex2f(emY[(size_t)(tn + 2) * NTAGS] * L2E); mY2 = mkY[tn + 2];
        fY3 = ex2f(emY[(size_t)(tn + 3) * NTAGS] * L2E); mY3 = mkY[tn + 3];
        crf_step2(eX0, eY0, qX0, qY0, 0, aX, aY, BaccX, BaccY, Epair, pbuf, j, half);
        crf_step2(eX1, eY1, qX1, qY1, 1, aX, aY, BaccX, BaccY, Epair, pbuf, j, half);
        crf_step2(eX2, eY2, qX2, qY2, 0, aX, aY, BaccX, BaccY, Epair, pbuf, j, half);
        crf_step2(eX3, eY3, qX3, qY3, 1, aX, aY, BaccX, BaccY, Epair, pbuf, j, half);
    }
    crf_step2(fX0, fY0, mX0, mY0, 0, aX, aY, BaccX, BaccY, Epair, pbuf, j, half);
    crf_step2(fX1, fY1, mX1, mY1, 1, aX, aY, BaccX, BaccY, Epair, pbuf, j, half);
    crf_step2(fX2, fY2, mX2, mY2, 0, aX, aY, BaccX, BaccY, Epair, pbuf, j, half);
    crf_step2(fX3, fY3, mX3, mY3, 1, aX, aY, BaccX, BaccY, Epair, pbuf, j, half);
    {
        float gX0 = ex2f(emX[(size_t)(SEQ - 3) * NTAGS] * L2E);
        float gX1 = ex2f(emX[(size_t)(SEQ - 2) * NTAGS] * L2E);
        float gX2 = ex2f(emX[(size_t)(SEQ - 1) * NTAGS] * L2E);
        float gY0 = ex2f(emY[(size_t)(SEQ - 3) * NTAGS] * L2E);
        float gY1 = ex2f(emY[(size_t)(SEQ - 2) * NTAGS] * L2E);
        float gY2 = ex2f(emY[(size_t)(SEQ - 1) * NTAGS] * L2E);
        int qXa = mkX[SEQ - 3], qXb = mkX[SEQ - 2], qXc = mkX[SEQ - 1];
        int qYa = mkY[SEQ - 3], qYb = mkY[SEQ - 2], qYc = mkY[SEQ - 1];
        crf_step2(gX0, gY0, qXa, qYa, 0, aX, aY, BaccX, BaccY, Epair, pbuf, j, half);
        crf_step2(gX1, gY1, qXb, qYb, 1, aX, aY, BaccX, BaccY, Epair, pbuf, j, half);
        crf_step2(gX2, gY2, qXc, qYc, 0, aX, aY, BaccX, BaccY, Epair, pbuf, j, half);
    }

    // log_z = ln2 * (Bacc + lg2(sum_j a_j * exp(end_j)))  (a_j > 0, bounded).
    float ee = __expf(endt[j]);
    if (half == 0) {              // outside the hot loop: branch cost irrelevant
        vredX[j] = aX * ee;
        vredY[j] = aY * ee;
    }
    __syncthreads();
    if (tid < 64) {
        int w = tid >> 5, l = tid & 31;
        const float* vr = w ? vredY : vredX;
        float s = vr[l] + vr[l + 32];
#pragma unroll
        for (int o = 16; o > 0; o >>= 1)
            s += __shfl_xor_sync(0xffffffffu, s, o);
        float Bw = w ? BaccY : BaccX;
        if (l == 0) g_logz[bX + w] = LN2 * (Bw + lg2f(s));
    }
}

// ---------- gold-path score: 1 block per batch ----------
__global__ void score_kernel(const float* __restrict__ em,
                             const float* __restrict__ startt,
                             const float* __restrict__ endt,
                             const float* __restrict__ trans,
                             const int* __restrict__ tags,
                             const int* __restrict__ mask)
{
    const int b = blockIdx.x;
    const int tid = threadIdx.x;  // 256
    const int* tg = tags + (size_t)b * SEQ;
    const int* mk = mask + (size_t)b * SEQ;
    const float* e = em + (size_t)b * SEQ * NTAGS;

    float acc = 0.0f;
    int cnt = 0;
    for (int t = tid; t < SEQ; t += 256) {
        int tag = tg[t];
        int mt = mk[t];
        cnt += (mt != 0);
        if (t == 0) {
            acc += startt[tag] + e[tag];
        } else if (mt) {
            int pv = tg[t - 1];
            acc += trans[pv * NTAGS + tag] + e[(size_t)t * NTAGS + tag];
        }
    }
    __shared__ float sacc[256];
    __shared__ int scnt[256];
    sacc[tid] = acc;
    scnt[tid] = cnt;
    __syncthreads();
    for (int o = 128; o > 0; o >>= 1) {
        if (tid < o) { sacc[tid] += sacc[tid + o]; scnt[tid] += scnt[tid + o]; }
        __syncthreads();
    }
    if (tid == 0) {
        int last = tg[scnt[0] - 1];
        g_score[b] = sacc[0] + endt[last];
    }
}

// ---------- deterministic final reduction ----------
__global__ void finalize_kernel(float* __restrict__ out)
{
    __shared__ float s[BATCH];
    int tid = threadIdx.x;
    s[tid] = g_logz[tid] - g_score[tid];
    __syncthreads();
    for (int o = BATCH / 2; o > 0; o >>= 1) {
        if (tid < o) s[tid] += s[tid + o];
        __syncthreads();
    }
    if (tid == 0) out[0] = s[0];
}

extern "C" void kernel_launch(void* const* d_in, const int* in_sizes, int n_in,
                              void* d_out, int out_size)
{
    const float* em      = (const float*)d_in[0];
    const float* startt  = (const float*)d_in[1];
    const float* endt    = (const float*)d_in[2];
    const float* trans   = (const float*)d_in[3];
    const int*   tags    = (const int*)d_in[4];
    const int*   mask    = (const int*)d_in[5];
    float* out = (float*)d_out;

    // forward first: keeps the bounded ncu capture window on it.
    forward_kernel<<<BATCH / 2, 128>>>(em, startt, endt, trans, mask);
    score_kernel<<<BATCH, 256>>>(em, startt, endt, trans, tags, mask);
    finalize_kernel<<<1, BATCH>>>(out);
}

// round 14
// speedup vs baseline: 1.3369x; 1.3369x over previous
#include <cuda_runtime.h>

#define BATCH 512
#define SEQ   1024
#define NTAGS 64
#define SEQNT (SEQ * NTAGS)

#define L2E 1.4426950408889634f
#define LN2 0.6931471805599453f

typedef unsigned long long ull;

__device__ float g_logz[BATCH];
__device__ float g_score[BATCH];

// ---------- packed f32x2 + MUFU helpers (sm_103a) ----------
__device__ __forceinline__ ull pack2(float a, float b) {
    ull r;
    unsigned ia = __float_as_uint(a), ib = __float_as_uint(b);
    asm("mov.b64 %0, {%1,%2};" : "=l"(r) : "r"(ia), "r"(ib));
    return r;
}
__device__ __forceinline__ void unpack2(ull v, float& a, float& b) {
    unsigned ia, ib;
    asm("mov.b64 {%0,%1}, %2;" : "=r"(ia), "=r"(ib) : "l"(v));
    a = __uint_as_float(ia);
    b = __uint_as_float(ib);
}
__device__ __forceinline__ ull fma2(ull a, ull b, ull c) {
    ull d;
    asm("fma.rn.f32x2 %0, %1, %2, %3;" : "=l"(d) : "l"(a), "l"(b), "l"(c));
    return d;
}
__device__ __forceinline__ ull add2(ull a, ull b) {
    ull d;
    asm("add.rn.f32x2 %0, %1, %2;" : "=l"(d) : "l"(a), "l"(b));
    return d;
}
__device__ __forceinline__ float ex2f(float x) {
    float r; asm("ex2.approx.f32 %0, %1;" : "=f"(r) : "f"(x)); return r;
}
__device__ __forceinline__ float lg2f(float x) {
    float r; asm("lg2.approx.f32 %0, %1;" : "=f"(r) : "f"(x)); return r;
}
__device__ __forceinline__ float rcpf(float x) {
    float r; asm("rcp.approx.f32 %0, %1;" : "=f"(r) : "f"(x)); return r;
}

// ---------- one step, TWO interleaved batches (probability domain) --------
// 64 threads/block, thread tid owns tag j = tid for batches X and Y.
// Invariant: true_log2_alpha_j = lg2(a_j) + Bacc (per batch; Bacc uniform).
// Ring passes RAW em floats; ex2 happens here (issued first, latency hidden
// under the dot). All control is SEL; stores unconditional.
__device__ __forceinline__ void crf_step2(
    float emrX, float emrY, int mkX, int mkY, int par,
    float& aX, float& aY, float& BaccX, float& BaccY,
    const ull (&E)[32],
    float (&pbuf)[2][2][64],
    int j)
{
    float eemX = ex2f(emrX * L2E);   // off-chain: needed only at dot end
    float eemY = ex2f(emrY * L2E);
    pbuf[par][0][j] = aX;            // one writer per address, no branches
    pbuf[par][1][j] = aY;
    __syncthreads();
    float a0X = pbuf[par][0][0];
    float a0Y = pbuf[par][1][0];
    const ulonglong2* pvX = reinterpret_cast<const ulonglong2*>(&pbuf[par][0][0]);
    const ulonglong2* pvY = reinterpret_cast<const ulonglong2*>(&pbuf[par][1][0]);
    ull sA = 0ull, sB = 0ull;        // X: 2 chains
    ull tA = 0ull, tB = 0ull;        // Y: 2 chains (4 total: enough ILP)
#pragma unroll
    for (int k = 0; k < 16; ++k) {   // broadcast LDS.128: all lanes same addr
        ulonglong2 qx = pvX[k];
        ulonglong2 qy = pvY[k];
        sA = fma2(qx.x, E[2 * k],     sA);
        tA = fma2(qy.x, E[2 * k],     tA);
        sB = fma2(qx.y, E[2 * k + 1], sB);
        tB = fma2(qy.y, E[2 * k + 1], tB);
    }
    float raX = rcpf(a0X), laX = lg2f(a0X);   // overlap the dot
    float raY = rcpf(a0Y), laY = lg2f(a0Y);
    ull sP = add2(sA, sB);
    ull tP = add2(tA, tB);
    float xlo, xhi, ylo, yhi;
    unpack2(sP, xlo, xhi);
    unpack2(tP, ylo, yhi);
    float nX = (xlo + xhi) * (eemX * raX);
    float nY = (ylo + yhi) * (eemY * raY);
    bool uX = (mkX != 0), uY = (mkY != 0);
    aX    = uX ? nX : aX;                     // SELs only
    BaccX = uX ? (BaccX + laX) : BaccX;
    aY    = uY ? nY : aY;
    BaccY = uY ? (BaccY + laY) : BaccY;
}

// ---------- forward algorithm: 2 contiguous batches per 64-thread block ---
__global__ void __launch_bounds__(64, 1)
forward_kernel(const float* __restrict__ em,
               const float* __restrict__ startt,
               const float* __restrict__ endt,
               const float* __restrict__ trans,
               const int* __restrict__ mask)
{
    __shared__ __align__(16) float pbuf[2][2][64];  // [par][batch][tag]
    __shared__ float vred[2][NTAGS];

    const int bX = 2 * blockIdx.x;                   // batches bX, bX+1
    const int j = threadIdx.x;                       // == tag

    // E column for tag j: exp(T[i][j]), packed f32x2 (64 regs, shared X/Y).
    ull E[32];
#pragma unroll
    for (int k = 0; k < 32; ++k) {
        float ea = __expf(trans[(2 * k)     * NTAGS + j]);
        float eb = __expf(trans[(2 * k + 1) * NTAGS + j]);
        E[k] = pack2(ea, eb);
    }

    // Single base pointers; batch Y reached via compile-time immediate offsets.
    const float* emB = em + (size_t)bX * SEQNT + j;
    const int* mkB = mask + (size_t)bX * SEQ;

    float st = startt[j] * L2E;
    float aX = ex2f(st + emB[0] * L2E);
    float aY = ex2f(st + emB[SEQNT] * L2E);
    float BaccX = 0.0f, BaccY = 0.0f;

    // Prefetch ring (RAW values only — no math at load site), distance 4.
    float rX0 = emB[(size_t)1 * NTAGS], rY0 = emB[(size_t)1 * NTAGS + SEQNT];
    float rX1 = emB[(size_t)2 * NTAGS], rY1 = emB[(size_t)2 * NTAGS + SEQNT];
    float rX2 = emB[(size_t)3 * NTAGS], rY2 = emB[(size_t)3 * NTAGS + SEQNT];
    float rX3 = emB[(size_t)4 * NTAGS], rY3 = emB[(size_t)4 * NTAGS + SEQNT];
    int mX0 = mkB[1], mY0 = mkB[1 + SEQ];
    int mX1 = mkB[2], mY1 = mkB[2 + SEQ];
    int mX2 = mkB[3], mY2 = mkB[3 + SEQ];
    int mX3 = mkB[4], mY3 = mkB[4 + SEQ];

    // Rotate-in-place: consume slot, then immediately reload it for t+4.
    for (int t0 = 1; t0 + 7 < SEQ; t0 += 4) {
        crf_step2(rX0, rY0, mX0, mY0, 0, aX, aY, BaccX, BaccY, E, pbuf, j);
        rX0 = emB[(size_t)(t0 + 4) * NTAGS];
        rY0 = emB[(size_t)(t0 + 4) * NTAGS + SEQNT];
        mX0 = mkB[t0 + 4]; mY0 = mkB[t0 + 4 + SEQ];
        crf_step2(rX1, rY1, mX1, mY1, 1, aX, aY, BaccX, BaccY, E, pbuf, j);
        rX1 = emB[(size_t)(t0 + 5) * NTAGS];
        rY1 = emB[(size_t)(t0 + 5) * NTAGS + SEQNT];
        mX1 = mkB[t0 + 5]; mY1 = mkB[t0 + 5 + SEQ];
        crf_step2(rX2, rY2, mX2, mY2, 0, aX, aY, BaccX, BaccY, E, pbuf, j);
        rX2 = emB[(size_t)(t0 + 6) * NTAGS];
        rY2 = emB[(size_t)(t0 + 6) * NTAGS + SEQNT];
        mX2 = mkB[t0 + 6]; mY2 = mkB[t0 + 6 + SEQ];
        crf_step2(rX3, rY3, mX3, mY3, 1, aX, aY, BaccX, BaccY, E, pbuf, j);
        rX3 = emB[(size_t)(t0 + 7) * NTAGS];
        rY3 = emB[(size_t)(t0 + 7) * NTAGS + SEQNT];
        mX3 = mkB[t0 + 7]; mY3 = mkB[t0 + 7 + SEQ];
    }
    // Tail: load the last 3 steps' data first (hidden under 4 ring steps).
    {
        float gX0 = emB[(size_t)(SEQ - 3) * NTAGS], gY0 = emB[(size_t)(SEQ - 3) * NTAGS + SEQNT];
        float gX1 = emB[(size_t)(SEQ - 2) * NTAGS], gY1 = emB[(size_t)(SEQ - 2) * NTAGS + SEQNT];
        float gX2 = emB[(size_t)(SEQ - 1) * NTAGS], gY2 = emB[(size_t)(SEQ - 1) * NTAGS + SEQNT];
        int qXa = mkB[SEQ - 3], qYa = mkB[SEQ - 3 + SEQ];
        int qXb = mkB[SEQ - 2], qYb = mkB[SEQ - 2 + SEQ];
        int qXc = mkB[SEQ - 1], qYc = mkB[SEQ - 1 + SEQ];
        crf_step2(rX0, rY0, mX0, mY0, 0, aX, aY, BaccX, BaccY, E, pbuf, j);
        crf_step2(rX1, rY1, mX1, mY1, 1, aX, aY, BaccX, BaccY, E, pbuf, j);
        crf_step2(rX2, rY2, mX2, mY2, 0, aX, aY, BaccX, BaccY, E, pbuf, j);
        crf_step2(rX3, rY3, mX3, mY3, 1, aX, aY, BaccX, BaccY, E, pbuf, j);
        crf_step2(gX0, gY0, qXa, qYa, 0, aX, aY, BaccX, BaccY, E, pbuf, j);
        crf_step2(gX1, gY1, qXb, qYb, 1, aX, aY, BaccX, BaccY, E, pbuf, j);
        crf_step2(gX2, gY2, qXc, qYc, 0, aX, aY, BaccX, BaccY, E, pbuf, j);
    }

    // log_z = ln2 * (Bacc + lg2(sum_j a_j * exp(end_j)));  warp w -> batch w.
    float ee = __expf(endt[j]);
    vred[0][j] = aX * ee;
    vred[1][j] = aY * ee;
    __syncthreads();
    {
        int w = j >> 5, l = j & 31;
        float s = vred[w][l] + vred[w][l + 32];
#pragma unroll
        for (int o = 16; o > 0; o >>= 1)
            s += __shfl_xor_sync(0xffffffffu, s, o);
        float Bw = w ? BaccY : BaccX;
        if (l == 0) g_logz[bX + w] = LN2 * (Bw + lg2f(s));
    }
}

// ---------- gold-path score: 1 block per batch ----------
__global__ void score_kernel(const float* __restrict__ em,
                             const float* __restrict__ startt,
                             const float* __restrict__ endt,
                             const float* __restrict__ trans,
                             const int* __restrict__ tags,
                             const int* __restrict__ mask)
{
    const int b = blockIdx.x;
    const int tid = threadIdx.x;  // 256
    const int* tg = tags + (size_t)b * SEQ;
    const int* mk = mask + (size_t)b * SEQ;
    const float* e = em + (size_t)b * SEQ * NTAGS;

    float acc = 0.0f;
    int cnt = 0;
    for (int t = tid; t < SEQ; t += 256) {
        int tag = tg[t];
        int mt = mk[t];
        cnt += (mt != 0);
        if (t == 0) {
            acc += startt[tag] + e[tag];
        } else if (mt) {
            int pv = tg[t - 1];
            acc += trans[pv * NTAGS + tag] + e[(size_t)t * NTAGS + tag];
        }
    }
    __shared__ float sacc[256];
    __shared__ int scnt[256];
    sacc[tid] = acc;
    scnt[tid] = cnt;
    __syncthreads();
    for (int o = 128; o > 0; o >>= 1) {
        if (tid < o) { sacc[tid] += sacc[tid + o]; scnt[tid] += scnt[tid + o]; }
        __syncthreads();
    }
    if (tid == 0) {
        int last = tg[scnt[0] - 1];
        g_score[b] = sacc[0] + endt[last];
    }
}

// ---------- deterministic final reduction ----------
__global__ void finalize_kernel(float* __restrict__ out)
{
    __shared__ float s[BATCH];
    int tid = threadIdx.x;
    s[tid] = g_logz[tid] - g_score[tid];
    __syncthreads();
    for (int o = BATCH / 2; o > 0; o >>= 1) {
        if (tid < o) s[tid] += s[tid + o];
        __syncthreads();
    }
    if (tid == 0) out[0] = s[0];
}

extern "C" void kernel_launch(void* const* d_in, const int* in_sizes, int n_in,
                              void* d_out, int out_size)
{
    const float* em      = (const float*)d_in[0];
    const float* startt  = (const float*)d_in[1];
    const float* endt    = (const float*)d_in[2];
    const float* trans   = (const float*)d_in[3];
    const int*   tags    = (const int*)d_in[4];
    const int*   mask    = (const int*)d_in[5];
    float* out = (float*)d_out;

    // forward first: keeps the bounded ncu capture window on it.
    forward_kernel<<<BATCH / 2, 64>>>(em, startt, endt, trans, mask);
    score_kernel<<<BATCH, 256>>>(em, startt, endt, trans, tags, mask);
    finalize_kernel<<<1, BATCH>>>(out);
}